// round 2
// baseline (speedup 1.0000x reference)
#include <cuda_runtime.h>
#include <cstdint>
#include <cstddef>

#define TT 512
#define BB 16
#define EE 1024
#define HH 512
#define G3 1536

// pre-gate scratch [d][t][r][b] and per-(dir,cta) step flags
__device__ float g_preg[(size_t)2 * TT * G3 * BB];
__device__ int   g_flag[128];

static __device__ __forceinline__ uint32_t f2tf(float f) {
    uint32_t r; asm("cvt.rna.tf32.f32 %0, %1;" : "=r"(r) : "f"(f)); return r;
}
static __device__ __forceinline__ float f2tff(float f) { return __uint_as_float(f2tf(f)); }

static __device__ __forceinline__ void mma8(float& d0, float& d1, float& d2, float& d3,
                                            uint32_t a0, uint32_t a1, uint32_t a2, uint32_t a3,
                                            uint32_t b0, uint32_t b1) {
    asm volatile(
        "mma.sync.aligned.m16n8k8.row.col.f32.tf32.tf32.f32 "
        "{%0,%1,%2,%3}, {%4,%5,%6,%7}, {%8,%9}, {%0,%1,%2,%3};"
        : "+f"(d0), "+f"(d1), "+f"(d2), "+f"(d3)
        : "r"(a0), "r"(a1), "r"(a2), "r"(a3), "r"(b0), "r"(b1));
}

static __device__ __forceinline__ int ld_acq(const int* p) {
    int v; asm volatile("ld.acquire.gpu.b32 %0, [%1];" : "=r"(v) : "l"(p) : "memory"); return v;
}
static __device__ __forceinline__ void st_rel(int* p, int v) {
    asm volatile("st.release.gpu.b32 [%0], %1;" :: "l"(p), "r"(v) : "memory");
}

__global__ void zero_flag_kernel() {
    int i = threadIdx.x;
    if (i < 128) g_flag[i] = 0;
}

// ---------------------------------------------------------------------------
// Phase 1: pre-gates = x @ W_x^T + bias for both directions (tf32 mma GEMM)
// M = T*B = 8192 (row = t*16+b), N = 1536, K = 1024. Tiles: 128x64x32.
// ---------------------------------------------------------------------------
__global__ __launch_bounds__(256) void pregemm_kernel(
    const float* __restrict__ x,
    const float* __restrict__ wf, const float* __restrict__ bf,
    const float* __restrict__ wb, const float* __restrict__ bb) {
    const int d = blockIdx.z;
    const float* __restrict__ w    = d ? wb : wf;
    const float* __restrict__ bias = d ? bb : bf;
    const int row0 = blockIdx.y * 128;
    const int col0 = blockIdx.x * 64;

    __shared__ float As[128][36];  // [m][k], pad 36 -> conflict-free frag loads
    __shared__ float Bs[64][36];   // [n][k]

    const int tid = threadIdx.x;
    const int lane = tid & 31, wid = tid >> 5;
    const int wm = wid >> 1, wn = wid & 1;
    const int g = lane >> 2, t4 = lane & 3;

    float acc[2][4][4];
#pragma unroll
    for (int i = 0; i < 2; i++)
#pragma unroll
        for (int j = 0; j < 4; j++)
#pragma unroll
            for (int r = 0; r < 4; r++) acc[i][j][r] = 0.f;

    for (int k0 = 0; k0 < EE; k0 += 32) {
#pragma unroll
        for (int i = 0; i < 4; i++) {
            int idx = tid + i * 256;
            int m = idx >> 3, kq = idx & 7;
            int row = row0 + m;
            int t = row >> 4, b = row & 15;
            float4 v = *reinterpret_cast<const float4*>(
                x + (size_t)(b * TT + t) * EE + k0 + kq * 4);
            float4 o = make_float4(f2tff(v.x), f2tff(v.y), f2tff(v.z), f2tff(v.w));
            *reinterpret_cast<float4*>(&As[m][kq * 4]) = o;
        }
#pragma unroll
        for (int i = 0; i < 2; i++) {
            int idx = tid + i * 256;
            int n = idx >> 3, kq = idx & 7;
            float4 v = *reinterpret_cast<const float4*>(
                w + (size_t)(col0 + n) * G3 + k0 + kq * 4);
            float4 o = make_float4(f2tff(v.x), f2tff(v.y), f2tff(v.z), f2tff(v.w));
            *reinterpret_cast<float4*>(&Bs[n][kq * 4]) = o;
        }
        __syncthreads();

#pragma unroll
        for (int kt = 0; kt < 4; kt++) {
            int k = kt * 8;
            uint32_t a[2][4];
#pragma unroll
            for (int mt = 0; mt < 2; mt++) {
                int mb = wm * 32 + mt * 16;
                a[mt][0] = __float_as_uint(As[mb + g][k + t4]);
                a[mt][1] = __float_as_uint(As[mb + g + 8][k + t4]);
                a[mt][2] = __float_as_uint(As[mb + g][k + 4 + t4]);
                a[mt][3] = __float_as_uint(As[mb + g + 8][k + 4 + t4]);
            }
#pragma unroll
            for (int nt = 0; nt < 4; nt++) {
                int nb = wn * 32 + nt * 8;
                uint32_t b0 = __float_as_uint(Bs[nb + g][k + t4]);
                uint32_t b1 = __float_as_uint(Bs[nb + g][k + 4 + t4]);
#pragma unroll
                for (int mt = 0; mt < 2; mt++)
                    mma8(acc[mt][nt][0], acc[mt][nt][1], acc[mt][nt][2], acc[mt][nt][3],
                         a[mt][0], a[mt][1], a[mt][2], a[mt][3], b0, b1);
            }
        }
        __syncthreads();
    }

#pragma unroll
    for (int mt = 0; mt < 2; mt++) {
        int rowb = row0 + wm * 32 + mt * 16 + g;
#pragma unroll
        for (int nt = 0; nt < 4; nt++) {
            int colb = col0 + wn * 32 + nt * 8 + 2 * t4;
#pragma unroll
            for (int r = 0; r < 4; r++) {
                int row = rowb + ((r >= 2) ? 8 : 0);
                int col = colb + (r & 1);
                int t = row >> 4, b = row & 15;
                float v = acc[mt][nt][r] + __ldg(bias + col);
                g_preg[(((size_t)d * TT + t) * G3 + col) * BB + b] = v;
            }
        }
    }
}

// ---------------------------------------------------------------------------
// Phase 2: persistent recurrence. 128 CTAs (64/dir, all resident), 128 thr.
// Each CTA: 8 h-columns => 24 gate rows (i/j/o), W_h tf32 in SMEM.
// Sync per step: per-CTA release-flag publish + 64-thread parallel
// acquire-poll (no contended atomics).
// ---------------------------------------------------------------------------
#define NWROWS 24
#define WPAD 516
#define RPAD 33

__global__ __launch_bounds__(128) void recur_kernel(
    const float* __restrict__ wf, const float* __restrict__ wb,
    const float* __restrict__ h0f, const float* __restrict__ h0b,
    const float* __restrict__ c0f, const float* __restrict__ c0b,
    float* __restrict__ out) {
    extern __shared__ float sm[];
    float* Wsm = sm;                     // 24*516
    float* hsm = Wsm + NWROWS * WPAD;    // 16*516
    float* red = hsm + 16 * WPAD;        // 4*16*33 = 2112

    const int d   = (int)blockIdx.x >> 6;
    const int grp = (int)blockIdx.x & 63;
    const int n0  = grp * 8;
    const float* __restrict__ w  = d ? wb : wf;
    const float* __restrict__ h0 = d ? h0b : h0f;
    const float* __restrict__ c0 = d ? c0b : c0f;
    const float* __restrict__ preg = g_preg + (size_t)d * TT * G3 * BB;
    int* flags = g_flag + d * 64;

    const int tid = threadIdx.x, lane = tid & 31, wid = tid >> 5;
    const int g = lane >> 2, t4 = lane & 3;
    const int eb = tid >> 3, en = tid & 7;  // epilogue (batch, col) ownership

    // Load this block's 24 W_h rows (k in [1024,1536) of W) as tf32 into SMEM
    for (int idx = tid; idx < NWROWS * 128; idx += 128) {
        int j = idx >> 7, kq = idx & 127;
        int r = (j < 8) ? (n0 + j) : ((j < 16) ? (512 + n0 + j - 8) : (1024 + n0 + j - 16));
        float4 v = *reinterpret_cast<const float4*>(w + (size_t)r * G3 + 1024 + kq * 4);
        float4 o = make_float4(f2tff(v.x), f2tff(v.y), f2tff(v.z), f2tff(v.w));
        *reinterpret_cast<float4*>(&Wsm[j * WPAD + kq * 4]) = o;
    }
    float c = c0[n0 + en];  // cell state lives in a register all 512 steps
    __syncthreads();

    for (int s = 0; s < TT; s++) {
        const int tt = d ? (TT - 1 - s) : s;

        // prefetch this step's pre-gate values BEFORE the wait (independent
        // of flags; their L2 latency hides under the spin)
        float pgi = __ldg(preg + ((size_t)tt * G3 + (n0 + en)) * BB + eb);
        float pgj = __ldg(preg + ((size_t)tt * G3 + (512 + n0 + en)) * BB + eb);
        float pgo = __ldg(preg + ((size_t)tt * G3 + (1024 + n0 + en)) * BB + eb);

        if (s > 0) {
            // 64 threads each poll one producer's flag (distinct addresses)
            if (tid < 64) {
                while (ld_acq(flags + tid) < s) {}
            }
            __syncthreads();
        }

        // fill hsm[16][512] with h_{t-1} (tf32-rounded)
        if (s == 0) {
            for (int idx = tid; idx < 16 * 128; idx += 128) {
                int b = idx >> 7, kq = idx & 127;
                float4 v = *reinterpret_cast<const float4*>(h0 + kq * 4);
                float4 o = make_float4(f2tff(v.x), f2tff(v.y), f2tff(v.z), f2tff(v.w));
                *reinterpret_cast<float4*>(&hsm[b * WPAD + kq * 4]) = o;
            }
        } else {
            const int tp = d ? (tt + 1) : (tt - 1);
            for (int idx = tid; idx < 16 * 128; idx += 128) {
                int b = idx >> 7, kq = idx & 127;
                float4 v = *reinterpret_cast<const float4*>(
                    out + (size_t)(b * TT + tp) * 1024 + d * 512 + kq * 4);
                float4 o = make_float4(f2tff(v.x), f2tff(v.y), f2tff(v.z), f2tff(v.w));
                *reinterpret_cast<float4*>(&hsm[b * WPAD + kq * 4]) = o;
            }
        }
        __syncthreads();

        // 4-warp K-split: warp wid covers k in [wid*128, wid*128+128)
        float acc[3][4];
#pragma unroll
        for (int nt = 0; nt < 3; nt++)
#pragma unroll
            for (int r = 0; r < 4; r++) acc[nt][r] = 0.f;

        const int kbase = wid * 128;
#pragma unroll
        for (int kt = 0; kt < 16; kt++) {
            int k = kbase + kt * 8;
            uint32_t a0 = __float_as_uint(hsm[g * WPAD + k + t4]);
            uint32_t a1 = __float_as_uint(hsm[(g + 8) * WPAD + k + t4]);
            uint32_t a2 = __float_as_uint(hsm[g * WPAD + k + 4 + t4]);
            uint32_t a3 = __float_as_uint(hsm[(g + 8) * WPAD + k + 4 + t4]);
#pragma unroll
            for (int nt = 0; nt < 3; nt++) {
                uint32_t b0 = __float_as_uint(Wsm[(nt * 8 + g) * WPAD + k + t4]);
                uint32_t b1 = __float_as_uint(Wsm[(nt * 8 + g) * WPAD + k + 4 + t4]);
                mma8(acc[nt][0], acc[nt][1], acc[nt][2], acc[nt][3],
                     a0, a1, a2, a3, b0, b1);
            }
        }

        // stash partials for cross-warp K reduction
#pragma unroll
        for (int nt = 0; nt < 3; nt++) {
            int rl = nt * 8 + 2 * t4;
            red[wid * 528 + g * RPAD + rl]           = acc[nt][0];
            red[wid * 528 + g * RPAD + rl + 1]       = acc[nt][1];
            red[wid * 528 + (g + 8) * RPAD + rl]     = acc[nt][2];
            red[wid * 528 + (g + 8) * RPAD + rl + 1] = acc[nt][3];
        }
        __syncthreads();

        // epilogue: each thread owns exactly one (b, n) output
        float si = pgi, sj = pgj, so = pgo;
#pragma unroll
        for (int wq = 0; wq < 4; wq++) {
            si += red[wq * 528 + eb * RPAD + en];
            sj += red[wq * 528 + eb * RPAD + 8 + en];
            so += red[wq * 528 + eb * RPAD + 16 + en];
        }
        float ig = 1.f / (1.f + __expf(-si));
        float cj = tanhf(sj);
        c = (1.f - ig) * c + ig * cj;                       // coupled gate
        float h = tanhf(c) * (1.f / (1.f + __expf(-so)));
        out[(size_t)(eb * TT + tt) * 1024 + d * 512 + n0 + en] = h;

        // publish: all h stores done -> cumulative fence -> release flag
        __syncthreads();
        if (tid == 0) {
            __threadfence();
            st_rel(flags + grp, s + 1);
        }
    }
}

extern "C" void kernel_launch(void* const* d_in, const int* in_sizes, int n_in,
                              void* d_out, int out_size) {
    (void)in_sizes; (void)n_in; (void)out_size;
    const float* x   = (const float*)d_in[0];
    const float* wf  = (const float*)d_in[1];
    const float* bf  = (const float*)d_in[2];
    const float* wb  = (const float*)d_in[3];
    const float* bb  = (const float*)d_in[4];
    const float* h0f = (const float*)d_in[5];
    const float* h0b = (const float*)d_in[6];
    const float* c0f = (const float*)d_in[7];
    const float* c0b = (const float*)d_in[8];
    float* out = (float*)d_out;

    const int smem_bytes = (NWROWS * WPAD + 16 * WPAD + 4 * 528) * 4;  // 91008
    cudaFuncSetAttribute(recur_kernel, cudaFuncAttributeMaxDynamicSharedMemorySize,
                         smem_bytes);

    zero_flag_kernel<<<1, 128>>>();
    dim3 g1(G3 / 64, (TT * BB) / 128, 2);
    pregemm_kernel<<<g1, 256>>>(x, wf, bf, wb, bb);
    recur_kernel<<<128, 128, smem_bytes>>>(wf, wb, h0f, h0b, c0f, c0b, out);
}

// round 3
// speedup vs baseline: 1.6093x; 1.6093x over previous
#include <cuda_runtime.h>
#include <cstdint>
#include <cstddef>

#define TT 512
#define BB 16
#define EE 1024
#define HH 512
#define G3 1536

// pre-gate scratch [d][t][r][b]; per-(dir,cta) step flags, one 128B line each
__device__ float g_preg[(size_t)2 * TT * G3 * BB];
__device__ int   g_flag[2 * 64 * 32];

static __device__ __forceinline__ uint32_t f2tf(float f) {
    uint32_t r; asm("cvt.rna.tf32.f32 %0, %1;" : "=r"(r) : "f"(f)); return r;
}
static __device__ __forceinline__ float f2tff(float f) { return __uint_as_float(f2tf(f)); }

static __device__ __forceinline__ void mma8(float& d0, float& d1, float& d2, float& d3,
                                            uint32_t a0, uint32_t a1, uint32_t a2, uint32_t a3,
                                            uint32_t b0, uint32_t b1) {
    asm volatile(
        "mma.sync.aligned.m16n8k8.row.col.f32.tf32.tf32.f32 "
        "{%0,%1,%2,%3}, {%4,%5,%6,%7}, {%8,%9}, {%0,%1,%2,%3};"
        : "+f"(d0), "+f"(d1), "+f"(d2), "+f"(d3)
        : "r"(a0), "r"(a1), "r"(a2), "r"(a3), "r"(b0), "r"(b1));
}

static __device__ __forceinline__ int ld_acq(const int* p) {
    int v; asm volatile("ld.acquire.gpu.b32 %0, [%1];" : "=r"(v) : "l"(p) : "memory"); return v;
}
static __device__ __forceinline__ void st_rel(int* p, int v) {
    asm volatile("st.release.gpu.b32 [%0], %1;" :: "l"(p), "r"(v) : "memory");
}

__global__ void zero_flag_kernel() {
    int i = blockIdx.x * blockDim.x + threadIdx.x;
    if (i < 2 * 64 * 32) g_flag[i] = 0;
}

// ---------------------------------------------------------------------------
// Phase 1: pre-gates = x @ W_x^T + bias for both directions (tf32 mma GEMM)
// M = T*B = 8192 (row = t*16+b), N = 1536, K = 1024. Tiles: 128x64x32.
// ---------------------------------------------------------------------------
__global__ __launch_bounds__(256) void pregemm_kernel(
    const float* __restrict__ x,
    const float* __restrict__ wf, const float* __restrict__ bf,
    const float* __restrict__ wb, const float* __restrict__ bb) {
    const int d = blockIdx.z;
    const float* __restrict__ w    = d ? wb : wf;
    const float* __restrict__ bias = d ? bb : bf;
    const int row0 = blockIdx.y * 128;
    const int col0 = blockIdx.x * 64;

    __shared__ float As[128][36];
    __shared__ float Bs[64][36];

    const int tid = threadIdx.x;
    const int lane = tid & 31, wid = tid >> 5;
    const int wm = wid >> 1, wn = wid & 1;
    const int g = lane >> 2, t4 = lane & 3;

    float acc[2][4][4];
#pragma unroll
    for (int i = 0; i < 2; i++)
#pragma unroll
        for (int j = 0; j < 4; j++)
#pragma unroll
            for (int r = 0; r < 4; r++) acc[i][j][r] = 0.f;

    for (int k0 = 0; k0 < EE; k0 += 32) {
#pragma unroll
        for (int i = 0; i < 4; i++) {
            int idx = tid + i * 256;
            int m = idx >> 3, kq = idx & 7;
            int row = row0 + m;
            int t = row >> 4, b = row & 15;
            float4 v = *reinterpret_cast<const float4*>(
                x + (size_t)(b * TT + t) * EE + k0 + kq * 4);
            float4 o = make_float4(f2tff(v.x), f2tff(v.y), f2tff(v.z), f2tff(v.w));
            *reinterpret_cast<float4*>(&As[m][kq * 4]) = o;
        }
#pragma unroll
        for (int i = 0; i < 2; i++) {
            int idx = tid + i * 256;
            int n = idx >> 3, kq = idx & 7;
            float4 v = *reinterpret_cast<const float4*>(
                w + (size_t)(col0 + n) * G3 + k0 + kq * 4);
            float4 o = make_float4(f2tff(v.x), f2tff(v.y), f2tff(v.z), f2tff(v.w));
            *reinterpret_cast<float4*>(&Bs[n][kq * 4]) = o;
        }
        __syncthreads();

#pragma unroll
        for (int kt = 0; kt < 4; kt++) {
            int k = kt * 8;
            uint32_t a[2][4];
#pragma unroll
            for (int mt = 0; mt < 2; mt++) {
                int mb = wm * 32 + mt * 16;
                a[mt][0] = __float_as_uint(As[mb + g][k + t4]);
                a[mt][1] = __float_as_uint(As[mb + g + 8][k + t4]);
                a[mt][2] = __float_as_uint(As[mb + g][k + 4 + t4]);
                a[mt][3] = __float_as_uint(As[mb + g + 8][k + 4 + t4]);
            }
#pragma unroll
            for (int nt = 0; nt < 4; nt++) {
                int nb = wn * 32 + nt * 8;
                uint32_t b0 = __float_as_uint(Bs[nb + g][k + t4]);
                uint32_t b1 = __float_as_uint(Bs[nb + g][k + 4 + t4]);
#pragma unroll
                for (int mt = 0; mt < 2; mt++)
                    mma8(acc[mt][nt][0], acc[mt][nt][1], acc[mt][nt][2], acc[mt][nt][3],
                         a[mt][0], a[mt][1], a[mt][2], a[mt][3], b0, b1);
            }
        }
        __syncthreads();
    }

#pragma unroll
    for (int mt = 0; mt < 2; mt++) {
        int rowb = row0 + wm * 32 + mt * 16 + g;
#pragma unroll
        for (int nt = 0; nt < 4; nt++) {
            int colb = col0 + wn * 32 + nt * 8 + 2 * t4;
#pragma unroll
            for (int r = 0; r < 4; r++) {
                int row = rowb + ((r >= 2) ? 8 : 0);
                int col = colb + (r & 1);
                int t = row >> 4, b = row & 15;
                float v = acc[mt][nt][r] + __ldg(bias + col);
                g_preg[(((size_t)d * TT + t) * G3 + col) * BB + b] = v;
            }
        }
    }
}

// ---------------------------------------------------------------------------
// Phase 2: persistent recurrence. 128 CTAs (64/dir), 128 thr, 1 CTA/SM.
// W_h fragments live in REGISTERS (96/thread). Per-thread poll of exactly
// the one producer whose h-columns this thread stages (flags on own lines,
// nanosleep backoff), merged with the h load; one barrier; 4-warp K-split
// tf32 mma; smem reduce; fused cell update; h -> d_out; fence + release.
// ---------------------------------------------------------------------------
#define WPAD 516
#define RPAD 33

__global__ __launch_bounds__(128) void recur_kernel(
    const float* __restrict__ wf, const float* __restrict__ wb,
    const float* __restrict__ h0f, const float* __restrict__ h0b,
    const float* __restrict__ c0f, const float* __restrict__ c0b,
    float* __restrict__ out) {
    __shared__ float hsm[16 * WPAD];   // h_{t-1} [b][k], tf32-rounded
    __shared__ float red[4 * 528];     // cross-warp K reduction

    const int d   = (int)blockIdx.x >> 6;
    const int grp = (int)blockIdx.x & 63;
    const int n0  = grp * 8;
    const float* __restrict__ w  = d ? wb : wf;
    const float* __restrict__ h0 = d ? h0b : h0f;
    const float* __restrict__ c0 = d ? c0b : c0f;
    const float* __restrict__ preg = g_preg + (size_t)d * TT * G3 * BB;
    int* flags = g_flag + d * 64 * 32;

    const int tid = threadIdx.x, lane = tid & 31, wid = tid >> 5;
    const int g = lane >> 2, t4 = lane & 3;
    const int eb = tid >> 3, en = tid & 7;   // epilogue (batch, col)
    const int pgrp = tid >> 1;               // producer whose columns I stage
    const int kbase = wid * 128;             // this warp's K slice

    // Preload this thread's W_h B-fragments into registers (tf32).
    // nt=0: i rows n0..n0+7; nt=1: j rows 512+n0..; nt=2: o rows 1024+n0..
    float breg[16][3][2];
#pragma unroll
    for (int nt = 0; nt < 3; nt++) {
        const float* wr = w + (size_t)(nt * 512 + n0 + g) * G3 + 1024;
#pragma unroll
        for (int kt = 0; kt < 16; kt++) {
            int col = kbase + kt * 8;
            breg[kt][nt][0] = f2tff(__ldg(wr + col + t4));
            breg[kt][nt][1] = f2tff(__ldg(wr + col + 4 + t4));
        }
    }
    float c = c0[n0 + en];  // cell state in a register for all 512 steps

    // step-0 h: broadcast h0 over batch
    {
        float4 v = *reinterpret_cast<const float4*>(h0 + tid * 4);
        float4 o = make_float4(f2tff(v.x), f2tff(v.y), f2tff(v.z), f2tff(v.w));
#pragma unroll
        for (int b = 0; b < 16; b++)
            *reinterpret_cast<float4*>(&hsm[b * WPAD + tid * 4]) = o;
    }
    __syncthreads();

    for (int s = 0; s < TT; s++) {
        const int tt = d ? (TT - 1 - s) : s;

        // pre-gate prefetch (ready in L2/DRAM; overlaps the poll below)
        float pgi = __ldg(preg + ((size_t)tt * G3 + (n0 + en)) * BB + eb);
        float pgj = __ldg(preg + ((size_t)tt * G3 + (512 + n0 + en)) * BB + eb);
        float pgo = __ldg(preg + ((size_t)tt * G3 + (1024 + n0 + en)) * BB + eb);

        if (s > 0) {
            // wait only for MY producer, then stage its 4 h-columns (all b)
            const int* fp = flags + pgrp * 32;
            if (ld_acq(fp) < s) {
                do { __nanosleep(32); } while (ld_acq(fp) < s);
            }
            const int tp = d ? (tt + 1) : (tt - 1);
            const float* src = out + (size_t)tp * 1024 + d * 512 + tid * 4;
#pragma unroll
            for (int b = 0; b < 16; b++) {
                float4 v = *reinterpret_cast<const float4*>(src + (size_t)b * TT * 1024);
                float4 o = make_float4(f2tff(v.x), f2tff(v.y), f2tff(v.z), f2tff(v.w));
                *reinterpret_cast<float4*>(&hsm[b * WPAD + tid * 4]) = o;
            }
        }
        __syncthreads();

        // 4-warp K-split mma: A from SMEM, B from registers
        float acc[3][4];
#pragma unroll
        for (int nt = 0; nt < 3; nt++)
#pragma unroll
            for (int r = 0; r < 4; r++) acc[nt][r] = 0.f;

#pragma unroll
        for (int kt = 0; kt < 16; kt++) {
            int k = kbase + kt * 8;
            uint32_t a0 = __float_as_uint(hsm[g * WPAD + k + t4]);
            uint32_t a1 = __float_as_uint(hsm[(g + 8) * WPAD + k + t4]);
            uint32_t a2 = __float_as_uint(hsm[g * WPAD + k + 4 + t4]);
            uint32_t a3 = __float_as_uint(hsm[(g + 8) * WPAD + k + 4 + t4]);
#pragma unroll
            for (int nt = 0; nt < 3; nt++)
                mma8(acc[nt][0], acc[nt][1], acc[nt][2], acc[nt][3],
                     a0, a1, a2, a3,
                     __float_as_uint(breg[kt][nt][0]),
                     __float_as_uint(breg[kt][nt][1]));
        }

        // cross-warp K reduction via SMEM
#pragma unroll
        for (int nt = 0; nt < 3; nt++) {
            int rl = nt * 8 + 2 * t4;
            red[wid * 528 + g * RPAD + rl]           = acc[nt][0];
            red[wid * 528 + g * RPAD + rl + 1]       = acc[nt][1];
            red[wid * 528 + (g + 8) * RPAD + rl]     = acc[nt][2];
            red[wid * 528 + (g + 8) * RPAD + rl + 1] = acc[nt][3];
        }
        __syncthreads();

        float si = pgi, sj = pgj, so = pgo;
#pragma unroll
        for (int wq = 0; wq < 4; wq++) {
            si += red[wq * 528 + eb * RPAD + en];
            sj += red[wq * 528 + eb * RPAD + 8 + en];
            so += red[wq * 528 + eb * RPAD + 16 + en];
        }
        float ig = 1.f / (1.f + __expf(-si));
        float cj = tanhf(sj);
        c = (1.f - ig) * c + ig * cj;                       // coupled gate
        float h = tanhf(c) * (1.f / (1.f + __expf(-so)));
        out[(size_t)(eb * TT + tt) * 1024 + d * 512 + n0 + en] = h;

        __syncthreads();
        if (tid == 0) {
            __threadfence();
            st_rel(flags + grp * 32, s + 1);
        }
    }
}

extern "C" void kernel_launch(void* const* d_in, const int* in_sizes, int n_in,
                              void* d_out, int out_size) {
    (void)in_sizes; (void)n_in; (void)out_size;
    const float* x   = (const float*)d_in[0];
    const float* wf  = (const float*)d_in[1];
    const float* bf  = (const float*)d_in[2];
    const float* wb  = (const float*)d_in[3];
    const float* bb  = (const float*)d_in[4];
    const float* h0f = (const float*)d_in[5];
    const float* h0b = (const float*)d_in[6];
    const float* c0f = (const float*)d_in[7];
    const float* c0b = (const float*)d_in[8];
    float* out = (float*)d_out;

    zero_flag_kernel<<<16, 256>>>();
    dim3 g1(G3 / 64, (TT * BB) / 128, 2);
    pregemm_kernel<<<g1, 256>>>(x, wf, bf, wb, bb);
    recur_kernel<<<128, 128>>>(wf, wb, h0f, h0b, c0f, c0b, out);
}

// round 4
// speedup vs baseline: 2.0724x; 1.2878x over previous
#include <cuda_runtime.h>
#include <cstdint>
#include <cstddef>

#define TT 512
#define BB 16
#define EE 1024
#define HH 512
#define G3 1536

// pre-gate scratch [d][t][col][b]
__device__ float g_preg[(size_t)2 * TT * G3 * BB];
// tf32-pre-rounded h staging [d][t][k][b]
__device__ float g_hstage[(size_t)2 * TT * HH * BB];
// per-(dir,cta) monotonic flags, one 128B line each (zero-init once per process)
__device__ int g_flag[2 * 64 * 32];

static __device__ __forceinline__ uint32_t f2tf(float f) {
    uint32_t r; asm("cvt.rna.tf32.f32 %0, %1;" : "=r"(r) : "f"(f)); return r;
}
static __device__ __forceinline__ float f2tff(float f) { return __uint_as_float(f2tf(f)); }

static __device__ __forceinline__ void mma8(float& d0, float& d1, float& d2, float& d3,
                                            uint32_t a0, uint32_t a1, uint32_t a2, uint32_t a3,
                                            uint32_t b0, uint32_t b1) {
    asm volatile(
        "mma.sync.aligned.m16n8k8.row.col.f32.tf32.tf32.f32 "
        "{%0,%1,%2,%3}, {%4,%5,%6,%7}, {%8,%9}, {%0,%1,%2,%3};"
        : "+f"(d0), "+f"(d1), "+f"(d2), "+f"(d3)
        : "r"(a0), "r"(a1), "r"(a2), "r"(a3), "r"(b0), "r"(b1));
}

static __device__ __forceinline__ int ld_acq(const int* p) {
    int v; asm volatile("ld.acquire.gpu.b32 %0, [%1];" : "=r"(v) : "l"(p) : "memory"); return v;
}
static __device__ __forceinline__ void red_rel_add1(int* p) {
    asm volatile("red.release.gpu.global.add.u32 [%0], %1;" :: "l"(p), "r"(1) : "memory");
}

// ---------------------------------------------------------------------------
// Phase 1: pre-gates = x @ W_x^T + bias, both directions (tf32 mma GEMM).
// M = 8192 (row = t*16+b), N = 1536, K = 1024. CTA tile 128x128x32,
// 8 warps (2x4), warp tile 64x32.
// ---------------------------------------------------------------------------
__global__ __launch_bounds__(256) void pregemm_kernel(
    const float* __restrict__ x,
    const float* __restrict__ wf, const float* __restrict__ bf,
    const float* __restrict__ wb, const float* __restrict__ bb) {
    const int d = blockIdx.z;
    const float* __restrict__ w    = d ? wb : wf;
    const float* __restrict__ bias = d ? bb : bf;
    const int row0 = blockIdx.y * 128;
    const int col0 = blockIdx.x * 128;

    __shared__ float As[128][36];
    __shared__ float Bs[128][36];

    const int tid = threadIdx.x;
    const int lane = tid & 31, wid = tid >> 5;
    const int wm = wid >> 2, wn = wid & 3;
    const int g = lane >> 2, t4 = lane & 3;

    float acc[4][4][4];
#pragma unroll
    for (int i = 0; i < 4; i++)
#pragma unroll
        for (int j = 0; j < 4; j++)
#pragma unroll
            for (int r = 0; r < 4; r++) acc[i][j][r] = 0.f;

    for (int k0 = 0; k0 < EE; k0 += 32) {
#pragma unroll
        for (int i = 0; i < 4; i++) {
            int idx = tid + i * 256;
            int m = idx >> 3, kq = idx & 7;
            int row = row0 + m;
            int t = row >> 4, b = row & 15;
            float4 v = *reinterpret_cast<const float4*>(
                x + (size_t)(b * TT + t) * EE + k0 + kq * 4);
            float4 o = make_float4(f2tff(v.x), f2tff(v.y), f2tff(v.z), f2tff(v.w));
            *reinterpret_cast<float4*>(&As[m][kq * 4]) = o;
        }
#pragma unroll
        for (int i = 0; i < 4; i++) {
            int idx = tid + i * 256;
            int n = idx >> 3, kq = idx & 7;
            float4 v = *reinterpret_cast<const float4*>(
                w + (size_t)(col0 + n) * G3 + k0 + kq * 4);
            float4 o = make_float4(f2tff(v.x), f2tff(v.y), f2tff(v.z), f2tff(v.w));
            *reinterpret_cast<float4*>(&Bs[n][kq * 4]) = o;
        }
        __syncthreads();

#pragma unroll
        for (int kt = 0; kt < 4; kt++) {
            int k = kt * 8;
            uint32_t a[4][4];
#pragma unroll
            for (int mt = 0; mt < 4; mt++) {
                int mb = wm * 64 + mt * 16;
                a[mt][0] = __float_as_uint(As[mb + g][k + t4]);
                a[mt][1] = __float_as_uint(As[mb + g + 8][k + t4]);
                a[mt][2] = __float_as_uint(As[mb + g][k + 4 + t4]);
                a[mt][3] = __float_as_uint(As[mb + g + 8][k + 4 + t4]);
            }
#pragma unroll
            for (int nt = 0; nt < 4; nt++) {
                int nb = wn * 32 + nt * 8;
                uint32_t b0 = __float_as_uint(Bs[nb + g][k + t4]);
                uint32_t b1 = __float_as_uint(Bs[nb + g][k + 4 + t4]);
#pragma unroll
                for (int mt = 0; mt < 4; mt++)
                    mma8(acc[mt][nt][0], acc[mt][nt][1], acc[mt][nt][2], acc[mt][nt][3],
                         a[mt][0], a[mt][1], a[mt][2], a[mt][3], b0, b1);
            }
        }
        __syncthreads();
    }

#pragma unroll
    for (int mt = 0; mt < 4; mt++) {
        int rowb = row0 + wm * 64 + mt * 16 + g;
#pragma unroll
        for (int nt = 0; nt < 4; nt++) {
            int colb = col0 + wn * 32 + nt * 8 + 2 * t4;
#pragma unroll
            for (int r = 0; r < 4; r++) {
                int row = rowb + ((r >= 2) ? 8 : 0);
                int col = colb + (r & 1);
                int t = row >> 4, b = row & 15;
                float v = acc[mt][nt][r] + __ldg(bias + col);
                g_preg[(((size_t)d * TT + t) * G3 + col) * BB + b] = v;
            }
        }
    }
}

// ---------------------------------------------------------------------------
// Phase 2: persistent recurrence. 128 CTAs (64/dir), 128 thr, 1 CTA/SM.
// W_h in registers. Publish = per-thread STG + red.release.add (no fence,
// no publish barrier). Consumers poll per-producer padded flags, read a
// compact tf32-pre-rounded staging buffer, 4x4-transpose into SMEM.
// ---------------------------------------------------------------------------
#define WPAD 516
#define RPAD 33

__global__ __launch_bounds__(128) void recur_kernel(
    const float* __restrict__ wf, const float* __restrict__ wb,
    const float* __restrict__ h0f, const float* __restrict__ h0b,
    const float* __restrict__ c0f, const float* __restrict__ c0b,
    float* __restrict__ out) {
    __shared__ float hsm[16 * WPAD];   // h_{t-1} [b][k], tf32-rounded
    __shared__ float red[4 * 528];     // cross-warp K reduction

    const int d   = (int)blockIdx.x >> 6;
    const int grp = (int)blockIdx.x & 63;
    const int n0  = grp * 8;
    const float* __restrict__ w  = d ? wb : wf;
    const float* __restrict__ h0 = d ? h0b : h0f;
    const float* __restrict__ c0 = d ? c0b : c0f;
    const float* __restrict__ preg = g_preg + (size_t)d * TT * G3 * BB;
    float* __restrict__ hst = g_hstage + (size_t)d * TT * HH * BB;
    int* flags = g_flag + d * 64 * 32;

    const int tid = threadIdx.x, lane = tid & 31, wid = tid >> 5;
    const int g = lane >> 2, t4 = lane & 3;
    const int eb = tid >> 3, en = tid & 7;   // epilogue (batch, col)
    const int pgrp = tid >> 1;               // producer whose flag I poll
    const int kbase = wid * 128;             // this warp's K slice
    const int k4 = tid * 4;                  // the 4 k-columns I stage

    // monotonic flag base (flags never reset; own flag untouched at entry)
    const int base = ld_acq(flags + grp * 32);

    // Preload this thread's W_h B-fragments into registers (tf32).
    float breg[16][3][2];
#pragma unroll
    for (int nt = 0; nt < 3; nt++) {
        const float* wr = w + (size_t)(nt * 512 + n0 + g) * G3 + 1024;
#pragma unroll
        for (int kt = 0; kt < 16; kt++) {
            int col = kbase + kt * 8;
            breg[kt][nt][0] = f2tff(__ldg(wr + col + t4));
            breg[kt][nt][1] = f2tff(__ldg(wr + col + 4 + t4));
        }
    }
    float c = c0[n0 + en];  // cell state in a register for all 512 steps

    // step-0 h: broadcast h0 over batch
    {
        float4 v = *reinterpret_cast<const float4*>(h0 + k4);
        float4 o = make_float4(f2tff(v.x), f2tff(v.y), f2tff(v.z), f2tff(v.w));
#pragma unroll
        for (int b = 0; b < 16; b++)
            *reinterpret_cast<float4*>(&hsm[b * WPAD + k4]) = o;
    }
    __syncthreads();

    for (int s = 0; s < TT; s++) {
        const int tt = d ? (TT - 1 - s) : s;

        // pre-gate prefetch (overlaps the poll below)
        float pgi = __ldg(preg + ((size_t)tt * G3 + (n0 + en)) * BB + eb);
        float pgj = __ldg(preg + ((size_t)tt * G3 + (512 + n0 + en)) * BB + eb);
        float pgo = __ldg(preg + ((size_t)tt * G3 + (1024 + n0 + en)) * BB + eb);

        if (s > 0) {
            // wait for MY producer's 128 release-increments for step s-1
            const int want = base + 128 * s;
            const int* fp = flags + pgrp * 32;
            while (ld_acq(fp) < want) {}

            // stage my 4 k-columns: contiguous 256B read, 4x4 reg transpose
            const int tp = d ? (tt + 1) : (tt - 1);
            const float* sp = hst + ((size_t)tp * HH + k4) * BB;
#pragma unroll
            for (int q = 0; q < 4; q++) {
                float4 v0 = *reinterpret_cast<const float4*>(sp + 0 * BB + q * 4);
                float4 v1 = *reinterpret_cast<const float4*>(sp + 1 * BB + q * 4);
                float4 v2 = *reinterpret_cast<const float4*>(sp + 2 * BB + q * 4);
                float4 v3 = *reinterpret_cast<const float4*>(sp + 3 * BB + q * 4);
                *reinterpret_cast<float4*>(&hsm[(q * 4 + 0) * WPAD + k4]) =
                    make_float4(v0.x, v1.x, v2.x, v3.x);
                *reinterpret_cast<float4*>(&hsm[(q * 4 + 1) * WPAD + k4]) =
                    make_float4(v0.y, v1.y, v2.y, v3.y);
                *reinterpret_cast<float4*>(&hsm[(q * 4 + 2) * WPAD + k4]) =
                    make_float4(v0.z, v1.z, v2.z, v3.z);
                *reinterpret_cast<float4*>(&hsm[(q * 4 + 3) * WPAD + k4]) =
                    make_float4(v0.w, v1.w, v2.w, v3.w);
            }
        }
        __syncthreads();

        // 4-warp K-split mma: A from SMEM, B from registers
        float acc[3][4];
#pragma unroll
        for (int nt = 0; nt < 3; nt++)
#pragma unroll
            for (int r = 0; r < 4; r++) acc[nt][r] = 0.f;

#pragma unroll
        for (int kt = 0; kt < 16; kt++) {
            int k = kbase + kt * 8;
            uint32_t a0 = __float_as_uint(hsm[g * WPAD + k + t4]);
            uint32_t a1 = __float_as_uint(hsm[(g + 8) * WPAD + k + t4]);
            uint32_t a2 = __float_as_uint(hsm[g * WPAD + k + 4 + t4]);
            uint32_t a3 = __float_as_uint(hsm[(g + 8) * WPAD + k + 4 + t4]);
#pragma unroll
            for (int nt = 0; nt < 3; nt++)
                mma8(acc[nt][0], acc[nt][1], acc[nt][2], acc[nt][3],
                     a0, a1, a2, a3,
                     __float_as_uint(breg[kt][nt][0]),
                     __float_as_uint(breg[kt][nt][1]));
        }

        // cross-warp K reduction via SMEM
#pragma unroll
        for (int nt = 0; nt < 3; nt++) {
            int rl = nt * 8 + 2 * t4;
            red[wid * 528 + g * RPAD + rl]           = acc[nt][0];
            red[wid * 528 + g * RPAD + rl + 1]       = acc[nt][1];
            red[wid * 528 + (g + 8) * RPAD + rl]     = acc[nt][2];
            red[wid * 528 + (g + 8) * RPAD + rl + 1] = acc[nt][3];
        }
        __syncthreads();

        float si = pgi, sj = pgj, so = pgo;
#pragma unroll
        for (int wq = 0; wq < 4; wq++) {
            si += red[wq * 528 + eb * RPAD + en];
            sj += red[wq * 528 + eb * RPAD + 8 + en];
            so += red[wq * 528 + eb * RPAD + 16 + en];
        }
        float ig = 1.f / (1.f + __expf(-si));
        float cj = tanhf(sj);
        c = (1.f - ig) * c + ig * cj;                       // coupled gate
        float h = tanhf(c) * (1.f / (1.f + __expf(-so)));

        // final output (off critical path) + tf32-rounded staging copy
        out[(size_t)(eb * TT + tt) * 1024 + d * 512 + n0 + en] = h;
        hst[((size_t)tt * HH + n0 + en) * BB + eb] = f2tff(h);

        // publish: my stores -> my release-increment (no fence, no barrier)
        red_rel_add1(flags + grp * 32);
    }
}

extern "C" void kernel_launch(void* const* d_in, const int* in_sizes, int n_in,
                              void* d_out, int out_size) {
    (void)in_sizes; (void)n_in; (void)out_size;
    const float* x   = (const float*)d_in[0];
    const float* wf  = (const float*)d_in[1];
    const float* bf  = (const float*)d_in[2];
    const float* wb  = (const float*)d_in[3];
    const float* bb  = (const float*)d_in[4];
    const float* h0f = (const float*)d_in[5];
    const float* h0b = (const float*)d_in[6];
    const float* c0f = (const float*)d_in[7];
    const float* c0b = (const float*)d_in[8];
    float* out = (float*)d_out;

    dim3 g1(G3 / 128, (TT * BB) / 128, 2);
    pregemm_kernel<<<g1, 256>>>(x, wf, bf, wb, bb);
    recur_kernel<<<128, 128>>>(wf, wb, h0f, h0b, c0f, c0b, out);
}

// round 5
// speedup vs baseline: 2.1057x; 1.0160x over previous
#include <cuda_runtime.h>
#include <cstdint>
#include <cstddef>

#define TT 512
#define BB 16
#define EE 1024
#define HH 512
#define G3 1536

// pre-gate scratch [d][t][col][b]
__device__ float g_preg[(size_t)2 * TT * G3 * BB];
// tf32-pre-rounded h staging [d][t][k][b]
__device__ float g_hstage[(size_t)2 * TT * HH * BB];
// per-(dir,cta) monotonic flags, one 128B line each
__device__ int g_flag[2 * 64 * 32];

static __device__ __forceinline__ uint32_t f2tf(float f) {
    uint32_t r; asm("cvt.rna.tf32.f32 %0, %1;" : "=r"(r) : "f"(f)); return r;
}
static __device__ __forceinline__ float f2tff(float f) { return __uint_as_float(f2tf(f)); }

static __device__ __forceinline__ void mma8(float& d0, float& d1, float& d2, float& d3,
                                            uint32_t a0, uint32_t a1, uint32_t a2, uint32_t a3,
                                            uint32_t b0, uint32_t b1) {
    asm volatile(
        "mma.sync.aligned.m16n8k8.row.col.f32.tf32.tf32.f32 "
        "{%0,%1,%2,%3}, {%4,%5,%6,%7}, {%8,%9}, {%0,%1,%2,%3};"
        : "+f"(d0), "+f"(d1), "+f"(d2), "+f"(d3)
        : "r"(a0), "r"(a1), "r"(a2), "r"(a3), "r"(b0), "r"(b1));
}

static __device__ __forceinline__ int ld_acq(const int* p) {
    int v; asm volatile("ld.acquire.gpu.b32 %0, [%1];" : "=r"(v) : "l"(p) : "memory"); return v;
}
static __device__ __forceinline__ int ld_rlx(const int* p) {
    int v; asm volatile("ld.relaxed.gpu.b32 %0, [%1];" : "=r"(v) : "l"(p) : "memory"); return v;
}
static __device__ __forceinline__ void red_rel_add1(int* p) {
    asm volatile("red.release.gpu.global.add.u32 [%0], %1;" :: "l"(p), "r"(1) : "memory");
}

// ---------------------------------------------------------------------------
// Phase 1: pre-gates = x @ W_x^T + bias, both directions (tf32 mma GEMM).
// M = 8192, N = 1536, K = 1024. CTA tile 128x128x32, 8 warps, warp 64x32.
// ---------------------------------------------------------------------------
__global__ __launch_bounds__(256) void pregemm_kernel(
    const float* __restrict__ x,
    const float* __restrict__ wf, const float* __restrict__ bf,
    const float* __restrict__ wb, const float* __restrict__ bb) {
    const int d = blockIdx.z;
    const float* __restrict__ w    = d ? wb : wf;
    const float* __restrict__ bias = d ? bb : bf;
    const int row0 = blockIdx.y * 128;
    const int col0 = blockIdx.x * 128;

    __shared__ float As[128][36];
    __shared__ float Bs[128][36];

    const int tid = threadIdx.x;
    const int lane = tid & 31, wid = tid >> 5;
    const int wm = wid >> 2, wn = wid & 3;
    const int g = lane >> 2, t4 = lane & 3;

    float acc[4][4][4];
#pragma unroll
    for (int i = 0; i < 4; i++)
#pragma unroll
        for (int j = 0; j < 4; j++)
#pragma unroll
            for (int r = 0; r < 4; r++) acc[i][j][r] = 0.f;

    for (int k0 = 0; k0 < EE; k0 += 32) {
#pragma unroll
        for (int i = 0; i < 4; i++) {
            int idx = tid + i * 256;
            int m = idx >> 3, kq = idx & 7;
            int row = row0 + m;
            int t = row >> 4, b = row & 15;
            float4 v = *reinterpret_cast<const float4*>(
                x + (size_t)(b * TT + t) * EE + k0 + kq * 4);
            float4 o = make_float4(f2tff(v.x), f2tff(v.y), f2tff(v.z), f2tff(v.w));
            *reinterpret_cast<float4*>(&As[m][kq * 4]) = o;
        }
#pragma unroll
        for (int i = 0; i < 4; i++) {
            int idx = tid + i * 256;
            int n = idx >> 3, kq = idx & 7;
            float4 v = *reinterpret_cast<const float4*>(
                w + (size_t)(col0 + n) * G3 + k0 + kq * 4);
            float4 o = make_float4(f2tff(v.x), f2tff(v.y), f2tff(v.z), f2tff(v.w));
            *reinterpret_cast<float4*>(&Bs[n][kq * 4]) = o;
        }
        __syncthreads();

#pragma unroll
        for (int kt = 0; kt < 4; kt++) {
            int k = kt * 8;
            uint32_t a[4][4];
#pragma unroll
            for (int mt = 0; mt < 4; mt++) {
                int mb = wm * 64 + mt * 16;
                a[mt][0] = __float_as_uint(As[mb + g][k + t4]);
                a[mt][1] = __float_as_uint(As[mb + g + 8][k + t4]);
                a[mt][2] = __float_as_uint(As[mb + g][k + 4 + t4]);
                a[mt][3] = __float_as_uint(As[mb + g + 8][k + 4 + t4]);
            }
#pragma unroll
            for (int nt = 0; nt < 4; nt++) {
                int nb = wn * 32 + nt * 8;
                uint32_t b0 = __float_as_uint(Bs[nb + g][k + t4]);
                uint32_t b1 = __float_as_uint(Bs[nb + g][k + 4 + t4]);
#pragma unroll
                for (int mt = 0; mt < 4; mt++)
                    mma8(acc[mt][nt][0], acc[mt][nt][1], acc[mt][nt][2], acc[mt][nt][3],
                         a[mt][0], a[mt][1], a[mt][2], a[mt][3], b0, b1);
            }
        }
        __syncthreads();
    }

#pragma unroll
    for (int mt = 0; mt < 4; mt++) {
        int rowb = row0 + wm * 64 + mt * 16 + g;
#pragma unroll
        for (int nt = 0; nt < 4; nt++) {
            int colb = col0 + wn * 32 + nt * 8 + 2 * t4;
#pragma unroll
            for (int r = 0; r < 4; r++) {
                int row = rowb + ((r >= 2) ? 8 : 0);
                int col = colb + (r & 1);
                int t = row >> 4, b = row & 15;
                float v = acc[mt][nt][r] + __ldg(bias + col);
                g_preg[(((size_t)d * TT + t) * G3 + col) * BB + b] = v;
            }
        }
    }
}

// ---------------------------------------------------------------------------
// Phase 2: persistent recurrence. 128 CTAs (64/dir), 128 thr, 1 CTA/SM.
// Per-warp decoupled waits: warp w's K-slice maps exactly to producers
// 16w..16w+15; each warp polls only those, stages its own hsm slice, and
// starts mma immediately. One CTA barrier per step (before the cross-warp
// reduce), red double-buffered by step parity. Publish: STG hst ->
// red.release (+1) -> STG out (out kept off the release-drain path).
// ---------------------------------------------------------------------------
#define WPAD 516
#define RPAD 33

__global__ __launch_bounds__(128) void recur_kernel(
    const float* __restrict__ wf, const float* __restrict__ wb,
    const float* __restrict__ h0f, const float* __restrict__ h0b,
    const float* __restrict__ c0f, const float* __restrict__ c0b,
    float* __restrict__ out) {
    __shared__ float hsm[16 * WPAD];    // h_{t-1} [b][k], tf32-rounded
    __shared__ float red[2 * 4 * 528];  // cross-warp K reduction, x2 parity

    const int d   = (int)blockIdx.x >> 6;
    const int grp = (int)blockIdx.x & 63;
    const int n0  = grp * 8;
    const float* __restrict__ w  = d ? wb : wf;
    const float* __restrict__ h0 = d ? h0b : h0f;
    const float* __restrict__ c0 = d ? c0b : c0f;
    const float* __restrict__ preg = g_preg + (size_t)d * TT * G3 * BB;
    float* __restrict__ hst = g_hstage + (size_t)d * TT * HH * BB;
    int* flags = g_flag + d * 64 * 32;

    const int tid = threadIdx.x, lane = tid & 31, wid = tid >> 5;
    const int g = lane >> 2, t4 = lane & 3;
    const int eb = tid >> 3, en = tid & 7;     // epilogue (batch, col)
    const int kbase = wid * 128;               // this warp's K slice
    const int k4 = tid * 4;                    // the 4 k-columns I stage
    const int myprod = wid * 16 + (lane >> 1); // producer this lane polls

    // monotonic flag base (all flags equal at launch entry)
    const int base = ld_acq(flags + grp * 32);
    const int* fp = flags + myprod * 32;

    // Preload this thread's W_h B-fragments into registers (tf32).
    float breg[16][3][2];
#pragma unroll
    for (int nt = 0; nt < 3; nt++) {
        const float* wr = w + (size_t)(nt * 512 + n0 + g) * G3 + 1024;
#pragma unroll
        for (int kt = 0; kt < 16; kt++) {
            int col = kbase + kt * 8;
            breg[kt][nt][0] = f2tff(__ldg(wr + col + t4));
            breg[kt][nt][1] = f2tff(__ldg(wr + col + 4 + t4));
        }
    }
    float c = c0[n0 + en];  // cell state in a register for all 512 steps

    // step-0 h: broadcast h0 over batch
    {
        float4 v = *reinterpret_cast<const float4*>(h0 + k4);
        float4 o = make_float4(f2tff(v.x), f2tff(v.y), f2tff(v.z), f2tff(v.w));
#pragma unroll
        for (int b = 0; b < 16; b++)
            *reinterpret_cast<float4*>(&hsm[b * WPAD + k4]) = o;
    }
    __syncthreads();

    for (int s = 0; s < TT; s++) {
        const int tt = d ? (TT - 1 - s) : s;
        const int par = s & 1;
        float* redp = red + par * (4 * 528);

        // pre-gate prefetch (independent; overlaps the poll below)
        float pgi = __ldg(preg + ((size_t)tt * G3 + (n0 + en)) * BB + eb);
        float pgj = __ldg(preg + ((size_t)tt * G3 + (512 + n0 + en)) * BB + eb);
        float pgo = __ldg(preg + ((size_t)tt * G3 + (1024 + n0 + en)) * BB + eb);

        if (s > 0) {
            // per-warp wait: only MY warp's 16 producers (2 lanes per flag)
            const int want = base + 128 * s;
            if (ld_acq(fp) < want) {
                while (ld_rlx(fp) < want) {}
                (void)ld_acq(fp);  // acquire to order the staged reads below
            }
            __syncwarp();

            // stage my 4 k-columns: contiguous 256B read, 4x4 reg transpose
            const int tp = d ? (tt + 1) : (tt - 1);
            const float* sp = hst + ((size_t)tp * HH + k4) * BB;
#pragma unroll
            for (int q = 0; q < 4; q++) {
                float4 v0 = *reinterpret_cast<const float4*>(sp + 0 * BB + q * 4);
                float4 v1 = *reinterpret_cast<const float4*>(sp + 1 * BB + q * 4);
                float4 v2 = *reinterpret_cast<const float4*>(sp + 2 * BB + q * 4);
                float4 v3 = *reinterpret_cast<const float4*>(sp + 3 * BB + q * 4);
                *reinterpret_cast<float4*>(&hsm[(q * 4 + 0) * WPAD + k4]) =
                    make_float4(v0.x, v1.x, v2.x, v3.x);
                *reinterpret_cast<float4*>(&hsm[(q * 4 + 1) * WPAD + k4]) =
                    make_float4(v0.y, v1.y, v2.y, v3.y);
                *reinterpret_cast<float4*>(&hsm[(q * 4 + 2) * WPAD + k4]) =
                    make_float4(v0.z, v1.z, v2.z, v3.z);
                *reinterpret_cast<float4*>(&hsm[(q * 4 + 3) * WPAD + k4]) =
                    make_float4(v0.w, v1.w, v2.w, v3.w);
            }
            __syncwarp();  // order STS before this warp's own LDS in mma
        }

        // per-warp mma on its own K slice: A from SMEM, B from registers
        float acc[3][4];
#pragma unroll
        for (int nt = 0; nt < 3; nt++)
#pragma unroll
            for (int r = 0; r < 4; r++) acc[nt][r] = 0.f;

#pragma unroll
        for (int kt = 0; kt < 16; kt++) {
            int k = kbase + kt * 8;
            uint32_t a0 = __float_as_uint(hsm[g * WPAD + k + t4]);
            uint32_t a1 = __float_as_uint(hsm[(g + 8) * WPAD + k + t4]);
            uint32_t a2 = __float_as_uint(hsm[g * WPAD + k + 4 + t4]);
            uint32_t a3 = __float_as_uint(hsm[(g + 8) * WPAD + k + 4 + t4]);
#pragma unroll
            for (int nt = 0; nt < 3; nt++)
                mma8(acc[nt][0], acc[nt][1], acc[nt][2], acc[nt][3],
                     a0, a1, a2, a3,
                     __float_as_uint(breg[kt][nt][0]),
                     __float_as_uint(breg[kt][nt][1]));
        }

        // cross-warp K reduction via SMEM (parity-buffered)
#pragma unroll
        for (int nt = 0; nt < 3; nt++) {
            int rl = nt * 8 + 2 * t4;
            redp[wid * 528 + g * RPAD + rl]           = acc[nt][0];
            redp[wid * 528 + g * RPAD + rl + 1]       = acc[nt][1];
            redp[wid * 528 + (g + 8) * RPAD + rl]     = acc[nt][2];
            redp[wid * 528 + (g + 8) * RPAD + rl + 1] = acc[nt][3];
        }
        __syncthreads();  // the single CTA-wide barrier per step

        float si = pgi, sj = pgj, so = pgo;
#pragma unroll
        for (int wq = 0; wq < 4; wq++) {
            si += redp[wq * 528 + eb * RPAD + en];
            sj += redp[wq * 528 + eb * RPAD + 8 + en];
            so += redp[wq * 528 + eb * RPAD + 16 + en];
        }
        float ig = 1.f / (1.f + __expf(-si));
        float cj = tanhf(sj);
        c = (1.f - ig) * c + ig * cj;                       // coupled gate
        float h = tanhf(c) * (1.f / (1.f + __expf(-so)));

        // publish: hst store -> release increment; out store stays off the
        // release-drain path (read only after kernel completion)
        hst[((size_t)tt * HH + n0 + en) * BB + eb] = f2tff(h);
        red_rel_add1(flags + grp * 32);
        out[(size_t)(eb * TT + tt) * 1024 + d * 512 + n0 + en] = h;
    }
}

extern "C" void kernel_launch(void* const* d_in, const int* in_sizes, int n_in,
                              void* d_out, int out_size) {
    (void)in_sizes; (void)n_in; (void)out_size;
    const float* x   = (const float*)d_in[0];
    const float* wf  = (const float*)d_in[1];
    const float* bf  = (const float*)d_in[2];
    const float* wb  = (const float*)d_in[3];
    const float* bb  = (const float*)d_in[4];
    const float* h0f = (const float*)d_in[5];
    const float* h0b = (const float*)d_in[6];
    const float* c0f = (const float*)d_in[7];
    const float* c0b = (const float*)d_in[8];
    float* out = (float*)d_out;

    dim3 g1(G3 / 128, (TT * BB) / 128, 2);
    pregemm_kernel<<<g1, 256>>>(x, wf, bf, wb, bb);
    recur_kernel<<<128, 128>>>(wf, wb, h0f, h0b, c0f, c0b, out);
}

// round 6
// speedup vs baseline: 2.5251x; 1.1992x over previous
#include <cuda_runtime.h>
#include <cstdint>
#include <cstddef>

#define TT 512
#define BB 16
#define EE 1024
#define HH 512
#define G3 1536
#define SENT 0x7FC00001u

// pre-gate scratch [d][t][col][b]
__device__ float g_preg[(size_t)2 * TT * G3 * BB];
// tf32-pre-rounded h staging [d][t][k][b]; sentinel-filled each launch
__device__ float g_hstage[(size_t)2 * TT * HH * BB];

static __device__ __forceinline__ uint32_t f2tf(float f) {
    uint32_t r; asm("cvt.rna.tf32.f32 %0, %1;" : "=r"(r) : "f"(f)); return r;
}
static __device__ __forceinline__ float f2tff(float f) { return __uint_as_float(f2tf(f)); }

static __device__ __forceinline__ void mma8(float& d0, float& d1, float& d2, float& d3,
                                            uint32_t a0, uint32_t a1, uint32_t a2, uint32_t a3,
                                            uint32_t b0, uint32_t b1) {
    asm volatile(
        "mma.sync.aligned.m16n8k8.row.col.f32.tf32.tf32.f32 "
        "{%0,%1,%2,%3}, {%4,%5,%6,%7}, {%8,%9}, {%0,%1,%2,%3};"
        : "+f"(d0), "+f"(d1), "+f"(d2), "+f"(d3)
        : "r"(a0), "r"(a1), "r"(a2), "r"(a3), "r"(b0), "r"(b1));
}

// L1-bypassing (gpu-scope) loads/stores for the producer-consumer handoff
static __device__ __forceinline__ float4 ld_rlx4(const float* p) {
    float4 v;
    asm volatile("ld.relaxed.gpu.global.v4.f32 {%0,%1,%2,%3}, [%4];"
                 : "=f"(v.x), "=f"(v.y), "=f"(v.z), "=f"(v.w) : "l"(p) : "memory");
    return v;
}
static __device__ __forceinline__ void st_rlx(float* p, float v) {
    asm volatile("st.relaxed.gpu.global.f32 [%0], %1;" :: "l"(p), "f"(v) : "memory");
}
static __device__ __forceinline__ bool has_sent(float4 v) {
    return (__float_as_uint(v.x) == SENT) | (__float_as_uint(v.y) == SENT) |
           (__float_as_uint(v.z) == SENT) | (__float_as_uint(v.w) == SENT);
}

// fill g_hstage with the sentinel pattern (runs first, every launch)
__global__ void fill_sentinel_kernel() {
    const size_t n4 = (size_t)2 * TT * HH * BB / 4;  // 2,097,152 uint4
    uint4 s = make_uint4(SENT, SENT, SENT, SENT);
    uint4* p = reinterpret_cast<uint4*>(g_hstage);
    for (size_t i = blockIdx.x * (size_t)blockDim.x + threadIdx.x; i < n4;
         i += (size_t)gridDim.x * blockDim.x)
        p[i] = s;
}

// ---------------------------------------------------------------------------
// Phase 1: pre-gates = x @ W_x^T + bias, both directions (tf32 mma GEMM).
// M = 8192, N = 1536, K = 1024. CTA tile 128x128x32, 8 warps, warp 64x32.
// ---------------------------------------------------------------------------
__global__ __launch_bounds__(256) void pregemm_kernel(
    const float* __restrict__ x,
    const float* __restrict__ wf, const float* __restrict__ bf,
    const float* __restrict__ wb, const float* __restrict__ bb) {
    const int d = blockIdx.z;
    const float* __restrict__ w    = d ? wb : wf;
    const float* __restrict__ bias = d ? bb : bf;
    const int row0 = blockIdx.y * 128;
    const int col0 = blockIdx.x * 128;

    __shared__ float As[128][36];
    __shared__ float Bs[128][36];

    const int tid = threadIdx.x;
    const int lane = tid & 31, wid = tid >> 5;
    const int wm = wid >> 2, wn = wid & 3;
    const int g = lane >> 2, t4 = lane & 3;

    float acc[4][4][4];
#pragma unroll
    for (int i = 0; i < 4; i++)
#pragma unroll
        for (int j = 0; j < 4; j++)
#pragma unroll
            for (int r = 0; r < 4; r++) acc[i][j][r] = 0.f;

    for (int k0 = 0; k0 < EE; k0 += 32) {
#pragma unroll
        for (int i = 0; i < 4; i++) {
            int idx = tid + i * 256;
            int m = idx >> 3, kq = idx & 7;
            int row = row0 + m;
            int t = row >> 4, b = row & 15;
            float4 v = *reinterpret_cast<const float4*>(
                x + (size_t)(b * TT + t) * EE + k0 + kq * 4);
            float4 o = make_float4(f2tff(v.x), f2tff(v.y), f2tff(v.z), f2tff(v.w));
            *reinterpret_cast<float4*>(&As[m][kq * 4]) = o;
        }
#pragma unroll
        for (int i = 0; i < 4; i++) {
            int idx = tid + i * 256;
            int n = idx >> 3, kq = idx & 7;
            float4 v = *reinterpret_cast<const float4*>(
                w + (size_t)(col0 + n) * G3 + k0 + kq * 4);
            float4 o = make_float4(f2tff(v.x), f2tff(v.y), f2tff(v.z), f2tff(v.w));
            *reinterpret_cast<float4*>(&Bs[n][kq * 4]) = o;
        }
        __syncthreads();

#pragma unroll
        for (int kt = 0; kt < 4; kt++) {
            int k = kt * 8;
            uint32_t a[4][4];
#pragma unroll
            for (int mt = 0; mt < 4; mt++) {
                int mb = wm * 64 + mt * 16;
                a[mt][0] = __float_as_uint(As[mb + g][k + t4]);
                a[mt][1] = __float_as_uint(As[mb + g + 8][k + t4]);
                a[mt][2] = __float_as_uint(As[mb + g][k + 4 + t4]);
                a[mt][3] = __float_as_uint(As[mb + g + 8][k + 4 + t4]);
            }
#pragma unroll
            for (int nt = 0; nt < 4; nt++) {
                int nb = wn * 32 + nt * 8;
                uint32_t b0 = __float_as_uint(Bs[nb + g][k + t4]);
                uint32_t b1 = __float_as_uint(Bs[nb + g][k + 4 + t4]);
#pragma unroll
                for (int mt = 0; mt < 4; mt++)
                    mma8(acc[mt][nt][0], acc[mt][nt][1], acc[mt][nt][2], acc[mt][nt][3],
                         a[mt][0], a[mt][1], a[mt][2], a[mt][3], b0, b1);
            }
        }
        __syncthreads();
    }

#pragma unroll
    for (int mt = 0; mt < 4; mt++) {
        int rowb = row0 + wm * 64 + mt * 16 + g;
#pragma unroll
        for (int nt = 0; nt < 4; nt++) {
            int colb = col0 + wn * 32 + nt * 8 + 2 * t4;
#pragma unroll
            for (int r = 0; r < 4; r++) {
                int row = rowb + ((r >= 2) ? 8 : 0);
                int col = colb + (r & 1);
                int t = row >> 4, b = row & 15;
                float v = acc[mt][nt][r] + __ldg(bias + col);
                g_preg[(((size_t)d * TT + t) * G3 + col) * BB + b] = v;
            }
        }
    }
}

// ---------------------------------------------------------------------------
// Phase 2: persistent recurrence. 128 CTAs (64/dir), 256 thr (8 warps),
// 1 CTA/SM. Data-as-flag: consumers poll the h staging lines themselves
// (sentinel NaN pattern). Each thread owns exactly one 128B line (2 k-cols
// x 16 batch). Each warp stages only its own K slice -> staging/mma are
// warp-autonomous; single CTA barrier per step before the parity-buffered
// cross-warp reduce. W_h fragments in registers (48/thread).
// ---------------------------------------------------------------------------
#define WPAD 516
#define RPAD 25

__global__ __launch_bounds__(256) void recur_kernel(
    const float* __restrict__ wf, const float* __restrict__ wb,
    const float* __restrict__ h0f, const float* __restrict__ h0b,
    const float* __restrict__ c0f, const float* __restrict__ c0b,
    float* __restrict__ out) {
    extern __shared__ float sm[];
    float* hsm = sm;                 // 16 x WPAD  (h_{t-1} [b][k])
    float* red = sm + 16 * WPAD;     // 2 x 8 x 16 x RPAD (parity-buffered)

    const int d   = (int)blockIdx.x >> 6;
    const int grp = (int)blockIdx.x & 63;
    const int n0  = grp * 8;
    const float* __restrict__ w  = d ? wb : wf;
    const float* __restrict__ h0 = d ? h0b : h0f;
    const float* __restrict__ c0 = d ? c0b : c0f;
    const float* __restrict__ preg = g_preg + (size_t)d * TT * G3 * BB;
    float* __restrict__ hst = g_hstage + (size_t)d * TT * HH * BB;

    const int tid = threadIdx.x, lane = tid & 31, wid = tid >> 5;
    const int g = lane >> 2, t4 = lane & 3;
    const int eb = (tid >> 3) & 15, en = tid & 7;  // epilogue (batch, col), tid<128
    const bool epi = tid < 128;
    const int kbase = wid * 64;       // this warp's K slice
    const int k2 = tid * 2;           // the 2 k-columns I stage (one 128B line)

    // Preload this thread's W_h B-fragments into registers (tf32).
    float breg[8][3][2];
#pragma unroll
    for (int nt = 0; nt < 3; nt++) {
        const float* wr = w + (size_t)(nt * 512 + n0 + g) * G3 + 1024;
#pragma unroll
        for (int kt = 0; kt < 8; kt++) {
            int col = kbase + kt * 8;
            breg[kt][nt][0] = f2tff(__ldg(wr + col + t4));
            breg[kt][nt][1] = f2tff(__ldg(wr + col + 4 + t4));
        }
    }
    float c = epi ? c0[n0 + en] : 0.f;  // cell state in a register

    // step-0 h: broadcast h0 over batch into my 2 columns
    {
        float2 o = make_float2(f2tff(h0[k2]), f2tff(h0[k2 + 1]));
#pragma unroll
        for (int b = 0; b < 16; b++)
            *reinterpret_cast<float2*>(&hsm[b * WPAD + k2]) = o;
    }
    __syncthreads();

    for (int s = 0; s < TT; s++) {
        const int tt = d ? (TT - 1 - s) : s;
        const int par = s & 1;
        float* redp = red + par * (8 * 16 * RPAD);

        // pre-gate prefetch (independent; overlaps the poll below)
        float pgi = 0.f, pgj = 0.f, pgo = 0.f;
        if (epi) {
            pgi = __ldg(preg + ((size_t)tt * G3 + (n0 + en)) * BB + eb);
            pgj = __ldg(preg + ((size_t)tt * G3 + (512 + n0 + en)) * BB + eb);
            pgo = __ldg(preg + ((size_t)tt * G3 + (1024 + n0 + en)) * BB + eb);
        }

        if (s > 0) {
            // poll MY line (data-as-flag): spin on first 16B, then verify all
            const int tp = d ? (tt + 1) : (tt - 1);
            const float* sp = hst + ((size_t)tp * HH + k2) * BB;
            float4 v[8];
            do { v[0] = ld_rlx4(sp); } while (has_sent(v[0]));
            for (;;) {
                bool bad = false;
#pragma unroll
                for (int q = 1; q < 8; q++) {
                    v[q] = ld_rlx4(sp + q * 4);
                    bad |= has_sent(v[q]);
                }
                if (!bad) break;
            }
            // transpose: v[0..3] = col k2 (b 0..15), v[4..7] = col k2+1
#pragma unroll
            for (int q = 0; q < 4; q++) {
                const float* a = &v[q].x;
                const float* bq = &v[4 + q].x;
#pragma unroll
                for (int r = 0; r < 4; r++)
                    *reinterpret_cast<float2*>(&hsm[(q * 4 + r) * WPAD + k2]) =
                        make_float2(a[r], bq[r]);
            }
        }
        __syncwarp();  // my warp's staging visible to my warp's mma

        // per-warp mma on its own K slice: A from SMEM, B from registers
        float acc[3][4];
#pragma unroll
        for (int nt = 0; nt < 3; nt++)
#pragma unroll
            for (int r = 0; r < 4; r++) acc[nt][r] = 0.f;

#pragma unroll
        for (int kt = 0; kt < 8; kt++) {
            int k = kbase + kt * 8;
            uint32_t a0 = __float_as_uint(hsm[g * WPAD + k + t4]);
            uint32_t a1 = __float_as_uint(hsm[(g + 8) * WPAD + k + t4]);
            uint32_t a2 = __float_as_uint(hsm[g * WPAD + k + 4 + t4]);
            uint32_t a3 = __float_as_uint(hsm[(g + 8) * WPAD + k + 4 + t4]);
#pragma unroll
            for (int nt = 0; nt < 3; nt++)
                mma8(acc[nt][0], acc[nt][1], acc[nt][2], acc[nt][3],
                     a0, a1, a2, a3,
                     __float_as_uint(breg[kt][nt][0]),
                     __float_as_uint(breg[kt][nt][1]));
        }

        // cross-warp K reduction via SMEM (parity-buffered)
        float* rw = redp + wid * 16 * RPAD;
#pragma unroll
        for (int nt = 0; nt < 3; nt++) {
            int rl = nt * 8 + 2 * t4;
            rw[g * RPAD + rl]           = acc[nt][0];
            rw[g * RPAD + rl + 1]       = acc[nt][1];
            rw[(g + 8) * RPAD + rl]     = acc[nt][2];
            rw[(g + 8) * RPAD + rl + 1] = acc[nt][3];
        }
        __syncthreads();  // the single CTA-wide barrier per step

        if (epi) {
            float si = pgi, sj = pgj, so = pgo;
#pragma unroll
            for (int wq = 0; wq < 8; wq++) {
                const float* rr = redp + (wq * 16 + eb) * RPAD;
                si += rr[en];
                sj += rr[8 + en];
                so += rr[16 + en];
            }
            float ig = 1.f / (1.f + __expf(-si));
            float cj = tanhf(sj);
            c = (1.f - ig) * c + ig * cj;                       // coupled gate
            float h = tanhf(c) * (1.f / (1.f + __expf(-so)));

            // publish: tf32-rounded h to the staging buffer (L2-direct),
            // full-precision h to the final output
            st_rlx(hst + ((size_t)tt * HH + n0 + en) * BB + eb, f2tff(h));
            out[(size_t)(eb * TT + tt) * 1024 + d * 512 + n0 + en] = h;
        }
    }
}

extern "C" void kernel_launch(void* const* d_in, const int* in_sizes, int n_in,
                              void* d_out, int out_size) {
    (void)in_sizes; (void)n_in; (void)out_size;
    const float* x   = (const float*)d_in[0];
    const float* wf  = (const float*)d_in[1];
    const float* bf  = (const float*)d_in[2];
    const float* wb  = (const float*)d_in[3];
    const float* bb  = (const float*)d_in[4];
    const float* h0f = (const float*)d_in[5];
    const float* h0b = (const float*)d_in[6];
    const float* c0f = (const float*)d_in[7];
    const float* c0b = (const float*)d_in[8];
    float* out = (float*)d_out;

    const int smem_bytes = (16 * WPAD + 2 * 8 * 16 * RPAD) * 4;  // 58624
    cudaFuncSetAttribute(recur_kernel, cudaFuncAttributeMaxDynamicSharedMemorySize,
                         smem_bytes);

    fill_sentinel_kernel<<<512, 256>>>();
    dim3 g1(G3 / 128, (TT * BB) / 128, 2);
    pregemm_kernel<<<g1, 256>>>(x, wf, bf, wb, bb);
    recur_kernel<<<128, 256, smem_bytes>>>(wf, wb, h0f, h0b, c0f, c0b, out);
}